// round 6
// baseline (speedup 1.0000x reference)
#include <cuda_runtime.h>
#include <math_constants.h>

#define BB   32
#define NP   1024
#define KNN  20
#define NPTS (BB*NP)
#define NEDGE (NPTS*KNN)

// ---------------- scratch (device globals; no allocation allowed) ----------
__device__ int   g_idx[NPTS*KNN];
__device__ float g_p1[NPTS*64];
__device__ float g_q1[NPTS*64];
__device__ float g_f1[NPTS*64];
__device__ float g_norm[NPTS];
__device__ float g_p2[NPTS*128];
__device__ float g_q2[NPTS*128];
__device__ float g_f2[NPTS*128];
__device__ float g_pool[BB*512];

// ---------------- 1) fused kNN on xyz ----------------
__global__ void __launch_bounds__(256) knn3_kernel(const float* __restrict__ x) {
    __shared__ float sx[NP], sy[NP], sz[NP], sq[NP];
    int rowBase = blockIdx.x * 8;
    int b = rowBase >> 10;
    const float* xb = x + (size_t)b * NP * 3;
    for (int i = threadIdx.x; i < NP; i += 256) {
        float a0 = xb[i*3], a1 = xb[i*3+1], a2 = xb[i*3+2];
        sx[i] = a0; sy[i] = a1; sz[i] = a2;
        sq[i] = a0*a0 + a1*a1 + a2*a2;
    }
    __syncthreads();
    int warp = threadIdx.x >> 5, lane = threadIdx.x & 31;
    int n  = rowBase + warp;
    int nl = n & (NP - 1);
    float qx = sx[nl], qy = sy[nl], qz = sz[nl], qs = sq[nl];
    float v[32];
#pragma unroll
    for (int i = 0; i < 32; i++) {
        int m = lane + (i << 5);
        float d = qs + sq[m] - 2.0f * (qx*sx[m] + qy*sy[m] + qz*sz[m]);
        v[i] = (m == nl) ? CUDART_INF_F : d;
    }
    float bv = v[0]; int bi = 0;
#pragma unroll
    for (int i = 1; i < 32; i++) if (v[i] < bv) { bv = v[i]; bi = i; }
    for (int r = 0; r < KNN; r++) {
        float mv = bv; int mi = (bi << 5) | lane;
#pragma unroll
        for (int off = 16; off > 0; off >>= 1) {
            float ov = __shfl_down_sync(0xffffffffu, mv, off);
            int   oi = __shfl_down_sync(0xffffffffu, mi, off);
            if (ov < mv || (ov == mv && oi < mi)) { mv = ov; mi = oi; }
        }
        mi = __shfl_sync(0xffffffffu, mi, 0);
        if (lane == 0) g_idx[n * KNN + r] = mi;
        if ((mi & 31) == lane) {
            int slot = mi >> 5;
#pragma unroll
            for (int i = 0; i < 32; i++) if (i == slot) v[i] = CUDART_INF_F;
            bv = v[0]; bi = 0;
#pragma unroll
            for (int i = 1; i < 32; i++) if (v[i] < bv) { bv = v[i]; bi = i; }
        }
    }
}

// ---------------- 3) EdgeConv1 layer-1 split precompute (+ zero f1) --------
__global__ void pre1_kernel(const float* __restrict__ x,
                            const float* __restrict__ W1,
                            const float* __restrict__ b1) {
    int id = blockIdx.x * blockDim.x + threadIdx.x;
    if (id >= NPTS * 64) return;
    int n = id >> 6, t = id & 63;
    float x0 = x[n*3], x1 = x[n*3+1], x2 = x[n*3+2];
    float wa0 = W1[t],       wa1 = W1[64 + t],  wa2 = W1[128 + t];
    float wb0 = W1[192 + t], wb1 = W1[256 + t], wb2 = W1[320 + t];
    float q = x0*wb0 + x1*wb1 + x2*wb2;
    float p = b1[t] + x0*(wa0-wb0) + x1*(wa1-wb1) + x2*(wa2-wb2);
    g_p1[id] = p;
    g_q1[id] = q;
    g_f1[id] = 0.0f;
}

// ---------------- 4) EdgeConv1 fused 2-layer GEMM over 256-edge tiles ------
#define ETP 260
#define EC1_SMEM ((64*ETP + 4096 + 4096 + 64 + 64) * 4)
__global__ void __launch_bounds__(256, 2) ec1_kernel(const float* __restrict__ W2,
                                                     const float* __restrict__ b2,
                                                     const float* __restrict__ W3,
                                                     const float* __restrict__ b3) {
    extern __shared__ float sm[];
    float* ET  = sm;
    float* sW2 = sm + 64*ETP;
    float* sW3 = sW2 + 4096;
    float* sB2 = sW3 + 4096;
    float* sB3 = sB2 + 64;
    int tid = threadIdx.x;
    int tx = tid & 7, ty = tid >> 3;

    for (int i = tid; i < 4096; i += 256) { sW2[i] = W2[i]; sW3[i] = W3[i]; }
    if (tid < 64) { sB2[tid] = b2[tid]; sB3[tid] = b3[tid]; }

    int B0 = blockIdx.x * 256;
    int g  = B0 + tid;
    int p  = g / KNN;
    int b  = p >> 10;
    int j  = g_idx[g];
    const float* pr = g_p1 + (size_t)p * 64;
    const float* qr = g_q1 + ((size_t)(b << 10) + j) * 64;
    __syncthreads();
#pragma unroll
    for (int c = 0; c < 64; c += 4) {
        float4 pv = *(const float4*)(pr + c);
        float4 qv = *(const float4*)(qr + c);
        ET[(c+0)*ETP + tid] = fmaxf(pv.x + qv.x, 0.0f);
        ET[(c+1)*ETP + tid] = fmaxf(pv.y + qv.y, 0.0f);
        ET[(c+2)*ETP + tid] = fmaxf(pv.z + qv.z, 0.0f);
        ET[(c+3)*ETP + tid] = fmaxf(pv.w + qv.w, 0.0f);
    }
    __syncthreads();

    float acc[8][8];
#pragma unroll
    for (int i = 0; i < 8; i++)
#pragma unroll
        for (int jj = 0; jj < 8; jj++) acc[i][jj] = 0.0f;
#pragma unroll 4
    for (int k = 0; k < 64; k++) {
        float4 a0 = *(const float4*)(ET + k*ETP + ty*8);
        float4 a1 = *(const float4*)(ET + k*ETP + ty*8 + 4);
        float4 w0 = *(const float4*)(sW2 + k*64 + tx*8);
        float4 w1 = *(const float4*)(sW2 + k*64 + tx*8 + 4);
        float a[8] = {a0.x,a0.y,a0.z,a0.w,a1.x,a1.y,a1.z,a1.w};
        float w[8] = {w0.x,w0.y,w0.z,w0.w,w1.x,w1.y,w1.z,w1.w};
#pragma unroll
        for (int i = 0; i < 8; i++)
#pragma unroll
            for (int jj = 0; jj < 8; jj++) acc[i][jj] = fmaf(a[i], w[jj], acc[i][jj]);
    }
    float bv2[8], bv3[8];
#pragma unroll
    for (int jj = 0; jj < 8; jj++) { bv2[jj] = sB2[tx*8+jj]; bv3[jj] = sB3[tx*8+jj]; }
    __syncthreads();
#pragma unroll
    for (int jj = 0; jj < 8; jj++)
#pragma unroll
        for (int i = 0; i < 8; i++)
            ET[(tx*8+jj)*ETP + ty*8 + i] = fmaxf(acc[i][jj] + bv2[jj], 0.0f);
    __syncthreads();

#pragma unroll
    for (int i = 0; i < 8; i++)
#pragma unroll
        for (int jj = 0; jj < 8; jj++) acc[i][jj] = 0.0f;
#pragma unroll 4
    for (int k = 0; k < 64; k++) {
        float4 a0 = *(const float4*)(ET + k*ETP + ty*8);
        float4 a1 = *(const float4*)(ET + k*ETP + ty*8 + 4);
        float4 w0 = *(const float4*)(sW3 + k*64 + tx*8);
        float4 w1 = *(const float4*)(sW3 + k*64 + tx*8 + 4);
        float a[8] = {a0.x,a0.y,a0.z,a0.w,a1.x,a1.y,a1.z,a1.w};
        float w[8] = {w0.x,w0.y,w0.z,w0.w,w1.x,w1.y,w1.z,w1.w};
#pragma unroll
        for (int i = 0; i < 8; i++)
#pragma unroll
            for (int jj = 0; jj < 8; jj++) acc[i][jj] = fmaf(a[i], w[jj], acc[i][jj]);
    }
    __syncthreads();
#pragma unroll
    for (int i = 0; i < 8; i++) {
        float4 v0, v1;
        v0.x = acc[i][0] + bv3[0]; v0.y = acc[i][1] + bv3[1];
        v0.z = acc[i][2] + bv3[2]; v0.w = acc[i][3] + bv3[3];
        v1.x = acc[i][4] + bv3[4]; v1.y = acc[i][5] + bv3[5];
        v1.z = acc[i][6] + bv3[6]; v1.w = acc[i][7] + bv3[7];
        *(float4*)(ET + (ty*8+i)*64 + tx*8)     = v0;
        *(float4*)(ET + (ty*8+i)*64 + tx*8 + 4) = v1;
    }
    __syncthreads();

    int pFirst = B0 / KNN;
    int pLast  = (B0 + 255) / KNN;
    int nseg   = pLast - pFirst + 1;
    int ch = tid & 63;
    for (int s = tid >> 6; s < nseg; s += 4) {
        int pt = pFirst + s;
        int r0 = max(pt * KNN,       B0) - B0;
        int r1 = min(pt * KNN + KNN, B0 + 256) - B0;
        if (r0 >= r1) continue;
        float m = ET[r0*64 + ch];
        for (int r = r0 + 1; r < r1; r++) m = fmaxf(m, ET[r*64 + ch]);
        atomicMax((int*)&g_f1[(size_t)pt*64 + ch], __float_as_int(m));
    }
}

// ---------------- 4b) squared norms of f1 rows ------------------------------
__global__ void norm64_kernel() {
    int n = blockIdx.x * 256 + threadIdx.x;
    const float4* r = (const float4*)(g_f1 + (size_t)n * 64);
    float s = 0.0f;
#pragma unroll
    for (int i = 0; i < 16; i++) {
        float4 v = r[i];
        s += v.x*v.x + v.y*v.y + v.z*v.z + v.w*v.w;
    }
    g_norm[n] = s;
}

// ---------------- 5) FUSED dist64 + top-20: no g_D round trip ---------------
// grid (8, BB): block owns 128 rows of one batch vs all 1024 cols.
// SMEM floats: sA 8448 | sB 8448 | sD 128*129 | sVal 128*21 | sIdx 128*21 | snA 128 | snB 128
#define DK_SMEM (39040 * 4)
__global__ void __launch_bounds__(256) distknn_kernel() {
    extern __shared__ float sm[];
    float* sA   = sm;                 // [64 k][132]  A^T resident
    float* sB   = sm + 8448;          // [64 k][132]  B chunk^T
    float* sD   = sm + 16896;         // [128][129]   distance chunk
    float* sVal = sm + 33408;         // [128][21]    sorted top-20 (asc)
    int*   sIdx = (int*)(sm + 36096); // [128][21]
    float* snA  = sm + 38784;         // [128]
    float* snB  = sm + 38912;         // [128]
    int b  = blockIdx.y;
    int m0 = blockIdx.x * 128;        // batch-local row base
    int tid = threadIdx.x;
    int tx = tid & 15, ty = tid >> 4;
    const float* F = g_f1 + (size_t)b * NP * 64;

    // A resident (all 64 k)
#pragma unroll
    for (int l = 0; l < 32; l++) {
        int idx = l * 256 + tid;
        int r = idx >> 6, c = idx & 63;
        sA[c * 132 + r] = F[(size_t)(m0 + r) * 64 + c];
    }
    if (tid < 128) snA[tid] = g_norm[b*NP + m0 + tid];
    for (int i = tid; i < 128*21; i += 256) sVal[i] = CUDART_INF_F;
    float kth = CUDART_INF_F;         // per-row 20th-best cache (tid<128)

    for (int nc = 0; nc < 8; nc++) {
        int n0 = nc * 128;
        __syncthreads();              // sB free, sD consumed
#pragma unroll
        for (int l = 0; l < 32; l++) {
            int idx = l * 256 + tid;
            int r = idx >> 6, c = idx & 63;
            sB[c * 132 + r] = F[(size_t)(n0 + r) * 64 + c];
        }
        if (tid < 128) snB[tid] = g_norm[b*NP + n0 + tid];
        __syncthreads();

        float acc[8][8];
#pragma unroll
        for (int i = 0; i < 8; i++)
#pragma unroll
            for (int j = 0; j < 8; j++) acc[i][j] = 0.0f;
        for (int k = 0; k < 64; k++) {
            float4 a0 = *(const float4*)(sA + k * 132 + ty * 8);
            float4 a1 = *(const float4*)(sA + k * 132 + ty * 8 + 4);
            float4 c0 = *(const float4*)(sB + k * 132 + tx * 8);
            float4 c1 = *(const float4*)(sB + k * 132 + tx * 8 + 4);
            float a[8]  = {a0.x, a0.y, a0.z, a0.w, a1.x, a1.y, a1.z, a1.w};
            float bv[8] = {c0.x, c0.y, c0.z, c0.w, c1.x, c1.y, c1.z, c1.w};
#pragma unroll
            for (int i = 0; i < 8; i++)
#pragma unroll
                for (int j = 0; j < 8; j++) acc[i][j] = fmaf(a[i], bv[j], acc[i][j]);
        }
        // distances into sD (pitch 129), diagonal -> inf
#pragma unroll
        for (int i = 0; i < 8; i++) {
            int rl = ty*8 + i;
            float nai = snA[rl];
#pragma unroll
            for (int j = 0; j < 8; j++) {
                int cl = tx*8 + j;
                float d = nai + snB[cl] - 2.0f * acc[i][j];
                if (m0 + rl == n0 + cl) d = CUDART_INF_F;
                sD[rl * 129 + cl] = d;
            }
        }
        __syncthreads();

        // merge: thread r owns row r's running top-20 (stable, asc scan)
        if (tid < 128) {
            int r = tid;
            float* rv = sVal + r * 21;
            int*   ri = sIdx + r * 21;
            for (int c = 0; c < 128; c++) {
                float v = sD[r * 129 + c];
                if (v < kth) {
                    int pos = 19;
                    while (pos > 0 && rv[pos-1] > v) {
                        rv[pos] = rv[pos-1];
                        ri[pos] = ri[pos-1];
                        pos--;
                    }
                    rv[pos] = v;
                    ri[pos] = n0 + c;
                    kth = rv[19];
                }
            }
        }
    }
    __syncthreads();
    if (tid < 128) {
        int n = b*NP + m0 + tid;
#pragma unroll
        for (int k = 0; k < KNN; k++) g_idx[n * KNN + k] = sIdx[tid * 21 + k];
    }
}

// ---------------- 6) pre2 as GEMM: [p2|q2] = f1 @ [W4a-W4b | W4b] ----------
#define TS 132
#define PRE2_SMEM ((32*TS*2 + 128) * 4)
__global__ void __launch_bounds__(256) pre2_kernel(const float* __restrict__ W4,
                                                   const float* __restrict__ b4) {
    extern __shared__ float sm[];
    float* sAt = sm;
    float* sBt = sm + 32*TS;
    float* sBias = sm + 64*TS;
    int nblk = blockIdx.x;
    int m0 = blockIdx.y * 128;
    int tid = threadIdx.x;
    int tx = tid & 15, ty = tid >> 4;

    if (tid < 128) sBias[tid] = (nblk == 0) ? b4[tid] : 0.0f;

    float acc[8][8];
#pragma unroll
    for (int i = 0; i < 8; i++)
#pragma unroll
        for (int j = 0; j < 8; j++) acc[i][j] = 0.0f;

    for (int kc = 0; kc < 2; kc++) {
        __syncthreads();
#pragma unroll
        for (int l = 0; l < 16; l++) {
            int idx = l * 256 + tid;
            int r = idx >> 5, c = idx & 31;
            sAt[c * TS + r] = g_f1[(size_t)(m0 + r) * 64 + kc * 32 + c];
        }
#pragma unroll
        for (int l = 0; l < 16; l++) {
            int idx = l * 256 + tid;
            int nl = idx & 127, kk = idx >> 7;
            int k = kc * 32 + kk;
            float wb = W4[(64 + k) * 128 + nl];
            float w  = (nblk == 0) ? (W4[k * 128 + nl] - wb) : wb;
            sBt[kk * TS + nl] = w;
        }
        __syncthreads();
        for (int k = 0; k < 32; k++) {
            float4 a0 = *(const float4*)(sAt + k * TS + ty * 8);
            float4 a1 = *(const float4*)(sAt + k * TS + ty * 8 + 4);
            float4 c0 = *(const float4*)(sBt + k * TS + tx * 8);
            float4 c1 = *(const float4*)(sBt + k * TS + tx * 8 + 4);
            float a[8]  = {a0.x, a0.y, a0.z, a0.w, a1.x, a1.y, a1.z, a1.w};
            float bv[8] = {c0.x, c0.y, c0.z, c0.w, c1.x, c1.y, c1.z, c1.w};
#pragma unroll
            for (int i = 0; i < 8; i++)
#pragma unroll
                for (int j = 0; j < 8; j++) acc[i][j] = fmaf(a[i], bv[j], acc[i][j]);
        }
    }
    float* dst = (nblk == 0) ? g_p2 : g_q2;
    float bb[8];
#pragma unroll
    for (int j = 0; j < 8; j++) bb[j] = sBias[tx*8 + j];
#pragma unroll
    for (int i = 0; i < 8; i++) {
        float4 o0, o1;
        o0.x = acc[i][0] + bb[0]; o0.y = acc[i][1] + bb[1];
        o0.z = acc[i][2] + bb[2]; o0.w = acc[i][3] + bb[3];
        o1.x = acc[i][4] + bb[4]; o1.y = acc[i][5] + bb[5];
        o1.z = acc[i][6] + bb[6]; o1.w = acc[i][7] + bb[7];
        float* row = dst + (size_t)(m0 + ty*8 + i) * 128 + tx*8;
        *(float4*)row       = o0;
        *(float4*)(row + 4) = o1;
    }
}

// ---------------- 7) EdgeConv2: max_k relu(p + q) ---------------------------
__global__ void ec2_kernel() {
    int n = blockIdx.x, t = threadIdx.x;
    int b = n >> 10;
    float p = g_p2[(size_t)n * 128 + t];
    const int* idxp = g_idx + n * KNN;
    float best = 0.0f;
#pragma unroll
    for (int k = 0; k < KNN; k++) {
        int j = idxp[k];
        float q = g_q2[((size_t)(b << 10) + j) * 128 + t];
        best = fmaxf(best, p + q);
    }
    g_f2[(size_t)n * 128 + t] = best;
}

// ---------------- 8) pool: stream m-tiles, Wp resident, direct store --------
// grid (BB, 4): block owns (batch, 128 output cols); max over all 1024 points.
#define POOL_SMEM ((128*132 + 32*132 + 16*128) * 4)
__global__ void __launch_bounds__(256) pool_kernel(const float* __restrict__ Wp,
                                                   const float* __restrict__ bp) {
    extern __shared__ float sm[];
    float* sW   = sm;                  // [128 k][132]
    float* sA   = sm + 128*132;        // [32 k][132] f2 chunk
    float* sred = sm + 128*132 + 32*132;
    int b  = blockIdx.x;
    int n0 = blockIdx.y * 128;
    int tid = threadIdx.x;
    int tx = tid & 15, ty = tid >> 4;

    // Wp slice resident
#pragma unroll
    for (int l = 0; l < 64; l++) {
        int idx = l * 256 + tid;
        int k = idx >> 7, n = idx & 127;
        sW[k * 132 + n] = Wp[(size_t)k * 512 + n0 + n];
    }

    float colmax[8];
#pragma unroll
    for (int j = 0; j < 8; j++) colmax[j] = 0.0f;   // relu fold
    float bpv[8];
#pragma unroll
    for (int j = 0; j < 8; j++) bpv[j] = bp[n0 + tx*8 + j];

    for (int mt = 0; mt < 8; mt++) {
        int m0 = mt * 128;
        float acc[8][8];
#pragma unroll
        for (int i = 0; i < 8; i++)
#pragma unroll
            for (int j = 0; j < 8; j++) acc[i][j] = 0.0f;
        for (int kc = 0; kc < 4; kc++) {
            __syncthreads();
#pragma unroll
            for (int l = 0; l < 16; l++) {
                int idx = l * 256 + tid;
                int r = idx >> 5, c = idx & 31;
                sA[c * 132 + r] = g_f2[(size_t)(b*NP + m0 + r) * 128 + kc * 32 + c];
            }
            __syncthreads();
            for (int k = 0; k < 32; k++) {
                float4 a0 = *(const float4*)(sA + k * 132 + ty * 8);
                float4 a1 = *(const float4*)(sA + k * 132 + ty * 8 + 4);
                float4 c0 = *(const float4*)(sW + (kc*32 + k) * 132 + tx * 8);
                float4 c1 = *(const float4*)(sW + (kc*32 + k) * 132 + tx * 8 + 4);
                float a[8]  = {a0.x, a0.y, a0.z, a0.w, a1.x, a1.y, a1.z, a1.w};
                float bv[8] = {c0.x, c0.y, c0.z, c0.w, c1.x, c1.y, c1.z, c1.w};
#pragma unroll
                for (int i = 0; i < 8; i++)
#pragma unroll
                    for (int j = 0; j < 8; j++) acc[i][j] = fmaf(a[i], bv[j], acc[i][j]);
            }
        }
#pragma unroll
        for (int j = 0; j < 8; j++) {
            float cm = colmax[j];
#pragma unroll
            for (int i = 0; i < 8; i++) cm = fmaxf(cm, acc[i][j] + bpv[j]);
            colmax[j] = cm;
        }
    }
    // cross-thread (ty) reduction
#pragma unroll
    for (int j = 0; j < 8; j++) sred[ty * 128 + tx*8 + j] = colmax[j];
    __syncthreads();
    if (ty == 0) {
#pragma unroll
        for (int j = 0; j < 8; j++) {
            float cm = 0.0f;
#pragma unroll
            for (int yy = 0; yy < 16; yy++) cm = fmaxf(cm, sred[yy * 128 + tx*8 + j]);
            g_pool[b * 512 + n0 + tx*8 + j] = cm;
        }
    }
}

// ---------------- 9) classifier head ----------------------------------------
__global__ void head_kernel(const float* __restrict__ Wt1, const float* __restrict__ bt1,
                            const float* __restrict__ Wt2, const float* __restrict__ bt2,
                            float* __restrict__ out) {
    __shared__ float sp[512];
    __shared__ float st[256];
    int b = blockIdx.x, t = threadIdx.x;
    sp[t]       = g_pool[b * 512 + t];
    sp[256 + t] = g_pool[b * 512 + 256 + t];
    __syncthreads();
    float acc = bt1[t];
#pragma unroll 8
    for (int c = 0; c < 512; c++) acc = fmaf(sp[c], Wt1[c * 256 + t], acc);
    st[t] = fmaxf(acc, 0.0f);
    __syncthreads();
    if (t < 40) {
        float a2 = bt2[t];
#pragma unroll 8
        for (int c = 0; c < 256; c++) a2 = fmaf(st[c], Wt2[c * 40 + t], a2);
        out[b * 40 + t] = a2;
    }
}

// ---------------- launch -----------------------------------------------------
extern "C" void kernel_launch(void* const* d_in, const int* in_sizes, int n_in,
                              void* d_out, int out_size) {
    const float* x   = (const float*)d_in[0];
    const float* W1  = (const float*)d_in[2];
    const float* b1  = (const float*)d_in[3];
    const float* W2  = (const float*)d_in[4];
    const float* b2  = (const float*)d_in[5];
    const float* W3  = (const float*)d_in[6];
    const float* b3  = (const float*)d_in[7];
    const float* W4  = (const float*)d_in[8];
    const float* b4  = (const float*)d_in[9];
    const float* Wp  = (const float*)d_in[10];
    const float* bp  = (const float*)d_in[11];
    const float* Wt1 = (const float*)d_in[12];
    const float* bt1 = (const float*)d_in[13];
    const float* Wt2 = (const float*)d_in[14];
    const float* bt2 = (const float*)d_in[15];
    float* out = (float*)d_out;

    cudaFuncSetAttribute(ec1_kernel,     cudaFuncAttributeMaxDynamicSharedMemorySize, EC1_SMEM);
    cudaFuncSetAttribute(distknn_kernel, cudaFuncAttributeMaxDynamicSharedMemorySize, DK_SMEM);
    cudaFuncSetAttribute(pre2_kernel,    cudaFuncAttributeMaxDynamicSharedMemorySize, PRE2_SMEM);
    cudaFuncSetAttribute(pool_kernel,    cudaFuncAttributeMaxDynamicSharedMemorySize, POOL_SMEM);

    // Stage 1
    knn3_kernel<<<NPTS / 8, 256>>>(x);
    pre1_kernel<<<(NPTS * 64) / 256, 256>>>(x, W1, b1);
    ec1_kernel<<<NEDGE / 256, 256, EC1_SMEM>>>(W2, b2, W3, b3);

    // Stage 2 (fused distance+top-k; no g_D)
    norm64_kernel<<<NPTS / 256, 256>>>();
    distknn_kernel<<<dim3(8, BB), 256, DK_SMEM>>>();
    pre2_kernel<<<dim3(2, 256), 256, PRE2_SMEM>>>(W4, b4);
    ec2_kernel<<<NPTS, 128>>>();

    // Stage 3
    pool_kernel<<<dim3(BB, 4), 256, POOL_SMEM>>>(Wp, bp);
    head_kernel<<<BB, 256>>>(Wt1, bt1, Wt2, bt2, out);
}

// round 7
// speedup vs baseline: 1.4323x; 1.4323x over previous
#include <cuda_runtime.h>
#include <math_constants.h>

#define BB   32
#define NP   1024
#define KNN  20
#define NPTS (BB*NP)
#define NEDGE (NPTS*KNN)

// ---------------- scratch (device globals; no allocation allowed) ----------
__device__ float g_D[(size_t)BB*NP*NP];
__device__ int   g_idx[NPTS*KNN];
__device__ float g_p1[NPTS*64];
__device__ float g_q1[NPTS*64];
__device__ float g_f1[NPTS*64];
__device__ float g_norm[NPTS];
__device__ float g_p2[NPTS*128];
__device__ float g_q2[NPTS*128];
__device__ float g_f2[NPTS*128];
__device__ float g_pool[BB*512];

// ---------------- 1) fused kNN on xyz ----------------
__global__ void __launch_bounds__(256) knn3_kernel(const float* __restrict__ x) {
    __shared__ float sx[NP], sy[NP], sz[NP], sq[NP];
    int rowBase = blockIdx.x * 8;
    int b = rowBase >> 10;
    const float* xb = x + (size_t)b * NP * 3;
    for (int i = threadIdx.x; i < NP; i += 256) {
        float a0 = xb[i*3], a1 = xb[i*3+1], a2 = xb[i*3+2];
        sx[i] = a0; sy[i] = a1; sz[i] = a2;
        sq[i] = a0*a0 + a1*a1 + a2*a2;
    }
    __syncthreads();
    int warp = threadIdx.x >> 5, lane = threadIdx.x & 31;
    int n  = rowBase + warp;
    int nl = n & (NP - 1);
    float qx = sx[nl], qy = sy[nl], qz = sz[nl], qs = sq[nl];
    float v[32];
#pragma unroll
    for (int i = 0; i < 32; i++) {
        int m = lane + (i << 5);
        float d = qs + sq[m] - 2.0f * (qx*sx[m] + qy*sy[m] + qz*sz[m]);
        v[i] = (m == nl) ? CUDART_INF_F : d;
    }
    float bv = v[0]; int bi = 0;
#pragma unroll
    for (int i = 1; i < 32; i++) if (v[i] < bv) { bv = v[i]; bi = i; }
    for (int r = 0; r < KNN; r++) {
        float mv = bv; int mi = (bi << 5) | lane;
#pragma unroll
        for (int off = 16; off > 0; off >>= 1) {
            float ov = __shfl_down_sync(0xffffffffu, mv, off);
            int   oi = __shfl_down_sync(0xffffffffu, mi, off);
            if (ov < mv || (ov == mv && oi < mi)) { mv = ov; mi = oi; }
        }
        mi = __shfl_sync(0xffffffffu, mi, 0);
        if (lane == 0) g_idx[n * KNN + r] = mi;
        if ((mi & 31) == lane) {
            int slot = mi >> 5;
#pragma unroll
            for (int i = 0; i < 32; i++) if (i == slot) v[i] = CUDART_INF_F;
            bv = v[0]; bi = 0;
#pragma unroll
            for (int i = 1; i < 32; i++) if (v[i] < bv) { bv = v[i]; bi = i; }
        }
    }
}

// ---------------- 2) top-20 per row of g_D (self excluded here) ------------
__global__ void topk_kernel() {
    int row  = blockIdx.x * 8 + (threadIdx.x >> 5);
    int lane = threadIdx.x & 31;
    int nl = row & (NP - 1);
    const float* d = g_D + (size_t)row * NP;
    float v[32];
#pragma unroll
    for (int i = 0; i < 32; i++) {
        int m = lane + (i << 5);
        v[i] = (m == nl) ? CUDART_INF_F : d[m];
    }
    float bv = v[0]; int bi = 0;
#pragma unroll
    for (int i = 1; i < 32; i++) if (v[i] < bv) { bv = v[i]; bi = i; }
    for (int r = 0; r < KNN; r++) {
        float mv = bv; int mi = (bi << 5) | lane;
#pragma unroll
        for (int off = 16; off > 0; off >>= 1) {
            float ov = __shfl_down_sync(0xffffffffu, mv, off);
            int   oi = __shfl_down_sync(0xffffffffu, mi, off);
            if (ov < mv || (ov == mv && oi < mi)) { mv = ov; mi = oi; }
        }
        mi = __shfl_sync(0xffffffffu, mi, 0);
        if (lane == 0) g_idx[row * KNN + r] = mi;
        if ((mi & 31) == lane) {
            int slot = mi >> 5;
#pragma unroll
            for (int i = 0; i < 32; i++) if (i == slot) v[i] = CUDART_INF_F;
            bv = v[0]; bi = 0;
#pragma unroll
            for (int i = 1; i < 32; i++) if (v[i] < bv) { bv = v[i]; bi = i; }
        }
    }
}

// ---------------- 3) EdgeConv1 layer-1 split precompute (+ zero f1) --------
__global__ void pre1_kernel(const float* __restrict__ x,
                            const float* __restrict__ W1,
                            const float* __restrict__ b1) {
    int id = blockIdx.x * blockDim.x + threadIdx.x;
    if (id >= NPTS * 64) return;
    int n = id >> 6, t = id & 63;
    float x0 = x[n*3], x1 = x[n*3+1], x2 = x[n*3+2];
    float wa0 = W1[t],       wa1 = W1[64 + t],  wa2 = W1[128 + t];
    float wb0 = W1[192 + t], wb1 = W1[256 + t], wb2 = W1[320 + t];
    float q = x0*wb0 + x1*wb1 + x2*wb2;
    float p = b1[t] + x0*(wa0-wb0) + x1*(wa1-wb1) + x2*(wa2-wb2);
    g_p1[id] = p;
    g_q1[id] = q;
    g_f1[id] = 0.0f;
}

// ---------------- 4) EdgeConv1 fused 2-layer GEMM over 256-edge tiles ------
#define ETP 260
#define EC1_SMEM ((64*ETP + 4096 + 4096 + 64 + 64) * 4)
__global__ void __launch_bounds__(256, 2) ec1_kernel(const float* __restrict__ W2,
                                                     const float* __restrict__ b2,
                                                     const float* __restrict__ W3,
                                                     const float* __restrict__ b3) {
    extern __shared__ float sm[];
    float* ET  = sm;
    float* sW2 = sm + 64*ETP;
    float* sW3 = sW2 + 4096;
    float* sB2 = sW3 + 4096;
    float* sB3 = sB2 + 64;
    int tid = threadIdx.x;
    int tx = tid & 7, ty = tid >> 3;

    for (int i = tid; i < 4096; i += 256) { sW2[i] = W2[i]; sW3[i] = W3[i]; }
    if (tid < 64) { sB2[tid] = b2[tid]; sB3[tid] = b3[tid]; }

    int B0 = blockIdx.x * 256;
    int g  = B0 + tid;
    int p  = g / KNN;
    int b  = p >> 10;
    int j  = g_idx[g];
    const float* pr = g_p1 + (size_t)p * 64;
    const float* qr = g_q1 + ((size_t)(b << 10) + j) * 64;
    __syncthreads();
#pragma unroll
    for (int c = 0; c < 64; c += 4) {
        float4 pv = *(const float4*)(pr + c);
        float4 qv = *(const float4*)(qr + c);
        ET[(c+0)*ETP + tid] = fmaxf(pv.x + qv.x, 0.0f);
        ET[(c+1)*ETP + tid] = fmaxf(pv.y + qv.y, 0.0f);
        ET[(c+2)*ETP + tid] = fmaxf(pv.z + qv.z, 0.0f);
        ET[(c+3)*ETP + tid] = fmaxf(pv.w + qv.w, 0.0f);
    }
    __syncthreads();

    float acc[8][8];
#pragma unroll
    for (int i = 0; i < 8; i++)
#pragma unroll
        for (int jj = 0; jj < 8; jj++) acc[i][jj] = 0.0f;
#pragma unroll 4
    for (int k = 0; k < 64; k++) {
        float4 a0 = *(const float4*)(ET + k*ETP + ty*8);
        float4 a1 = *(const float4*)(ET + k*ETP + ty*8 + 4);
        float4 w0 = *(const float4*)(sW2 + k*64 + tx*8);
        float4 w1 = *(const float4*)(sW2 + k*64 + tx*8 + 4);
        float a[8] = {a0.x,a0.y,a0.z,a0.w,a1.x,a1.y,a1.z,a1.w};
        float w[8] = {w0.x,w0.y,w0.z,w0.w,w1.x,w1.y,w1.z,w1.w};
#pragma unroll
        for (int i = 0; i < 8; i++)
#pragma unroll
            for (int jj = 0; jj < 8; jj++) acc[i][jj] = fmaf(a[i], w[jj], acc[i][jj]);
    }
    float bv2[8], bv3[8];
#pragma unroll
    for (int jj = 0; jj < 8; jj++) { bv2[jj] = sB2[tx*8+jj]; bv3[jj] = sB3[tx*8+jj]; }
    __syncthreads();
#pragma unroll
    for (int jj = 0; jj < 8; jj++)
#pragma unroll
        for (int i = 0; i < 8; i++)
            ET[(tx*8+jj)*ETP + ty*8 + i] = fmaxf(acc[i][jj] + bv2[jj], 0.0f);
    __syncthreads();

#pragma unroll
    for (int i = 0; i < 8; i++)
#pragma unroll
        for (int jj = 0; jj < 8; jj++) acc[i][jj] = 0.0f;
#pragma unroll 4
    for (int k = 0; k < 64; k++) {
        float4 a0 = *(const float4*)(ET + k*ETP + ty*8);
        float4 a1 = *(const float4*)(ET + k*ETP + ty*8 + 4);
        float4 w0 = *(const float4*)(sW3 + k*64 + tx*8);
        float4 w1 = *(const float4*)(sW3 + k*64 + tx*8 + 4);
        float a[8] = {a0.x,a0.y,a0.z,a0.w,a1.x,a1.y,a1.z,a1.w};
        float w[8] = {w0.x,w0.y,w0.z,w0.w,w1.x,w1.y,w1.z,w1.w};
#pragma unroll
        for (int i = 0; i < 8; i++)
#pragma unroll
            for (int jj = 0; jj < 8; jj++) acc[i][jj] = fmaf(a[i], w[jj], acc[i][jj]);
    }
    __syncthreads();
#pragma unroll
    for (int i = 0; i < 8; i++) {
        float4 v0, v1;
        v0.x = acc[i][0] + bv3[0]; v0.y = acc[i][1] + bv3[1];
        v0.z = acc[i][2] + bv3[2]; v0.w = acc[i][3] + bv3[3];
        v1.x = acc[i][4] + bv3[4]; v1.y = acc[i][5] + bv3[5];
        v1.z = acc[i][6] + bv3[6]; v1.w = acc[i][7] + bv3[7];
        *(float4*)(ET + (ty*8+i)*64 + tx*8)     = v0;
        *(float4*)(ET + (ty*8+i)*64 + tx*8 + 4) = v1;
    }
    __syncthreads();

    int pFirst = B0 / KNN;
    int pLast  = (B0 + 255) / KNN;
    int nseg   = pLast - pFirst + 1;
    int ch = tid & 63;
    for (int s = tid >> 6; s < nseg; s += 4) {
        int pt = pFirst + s;
        int r0 = max(pt * KNN,       B0) - B0;
        int r1 = min(pt * KNN + KNN, B0 + 256) - B0;
        if (r0 >= r1) continue;
        float m = ET[r0*64 + ch];
        for (int r = r0 + 1; r < r1; r++) m = fmaxf(m, ET[r*64 + ch]);
        atomicMax((int*)&g_f1[(size_t)pt*64 + ch], __float_as_int(m));
    }
}

// ---------------- 4b) squared norms of f1 rows ------------------------------
__global__ void norm64_kernel() {
    int n = blockIdx.x * 256 + threadIdx.x;
    const float4* r = (const float4*)(g_f1 + (size_t)n * 64);
    float s = 0.0f;
#pragma unroll
    for (int i = 0; i < 16; i++) {
        float4 v = r[i];
        s += v.x*v.x + v.y*v.y + v.z*v.z + v.w*v.w;
    }
    g_norm[n] = s;
}

// ---------------- 5) dist64: SYMMETRIC Gram GEMM (ti<=tj), dual store -------
// grid (36, BB): 36 tile-pairs of 8x8 tiles per batch. Bitwise-identical D.
#define TS 132
#define D64_SMEM ((32*TS*2 + 256) * 4)
__global__ void __launch_bounds__(256) dist64_kernel() {
    extern __shared__ float sm[];
    float* sAt = sm;                 // [k][m] transposed tiles
    float* sBt = sm + 32*TS;
    float* snA = sm + 64*TS;
    float* snB = snA + 128;
    int b = blockIdx.y;
    // map blockIdx.x in [0,36) -> (ti, tj) with ti <= tj
    int t = blockIdx.x, ti = 0;
    while (t >= 8 - ti) { t -= 8 - ti; ti++; }
    int tj = ti + t;
    int m0 = ti * 128, n0 = tj * 128;
    int tid = threadIdx.x;
    int tx = tid & 15, ty = tid >> 4;
    const float* F = g_f1 + (size_t)b * NP * 64;

    if (tid < 128)      snA[tid]       = g_norm[b*NP + m0 + tid];
    else                snB[tid - 128] = g_norm[b*NP + n0 + tid - 128];

    float acc[8][8];
#pragma unroll
    for (int i = 0; i < 8; i++)
#pragma unroll
        for (int j = 0; j < 8; j++) acc[i][j] = 0.0f;

    for (int kc = 0; kc < 2; kc++) {
        __syncthreads();
#pragma unroll
        for (int l = 0; l < 16; l++) {
            int idx = l * 256 + tid;
            int r = idx >> 5, c = idx & 31;
            sAt[c * TS + r] = F[(size_t)(m0 + r) * 64 + kc * 32 + c];
            sBt[c * TS + r] = F[(size_t)(n0 + r) * 64 + kc * 32 + c];
        }
        __syncthreads();
        for (int k = 0; k < 32; k++) {
            float4 a0 = *(const float4*)(sAt + k * TS + ty * 8);
            float4 a1 = *(const float4*)(sAt + k * TS + ty * 8 + 4);
            float4 c0 = *(const float4*)(sBt + k * TS + tx * 8);
            float4 c1 = *(const float4*)(sBt + k * TS + tx * 8 + 4);
            float a[8]  = {a0.x, a0.y, a0.z, a0.w, a1.x, a1.y, a1.z, a1.w};
            float bv[8] = {c0.x, c0.y, c0.z, c0.w, c1.x, c1.y, c1.z, c1.w};
#pragma unroll
            for (int i = 0; i < 8; i++)
#pragma unroll
                for (int j = 0; j < 8; j++) acc[i][j] = fmaf(a[i], bv[j], acc[i][j]);
        }
    }
    float* Dp = g_D + (size_t)b * NP * NP;
    float nb_[8];
#pragma unroll
    for (int j = 0; j < 8; j++) nb_[j] = snB[tx*8 + j];

    float dv[8][8];
#pragma unroll
    for (int i = 0; i < 8; i++) {
        float nai = snA[ty*8 + i];
#pragma unroll
        for (int j = 0; j < 8; j++) dv[i][j] = nai + nb_[j] - 2.0f * acc[i][j];
    }
    // row-major store of the (m0,n0) tile
#pragma unroll
    for (int i = 0; i < 8; i++) {
        float* row = Dp + (size_t)(m0 + ty*8 + i) * NP + n0 + tx*8;
        *(float4*)row       = make_float4(dv[i][0], dv[i][1], dv[i][2], dv[i][3]);
        *(float4*)(row + 4) = make_float4(dv[i][4], dv[i][5], dv[i][6], dv[i][7]);
    }
    if (ti != tj) {
        // transposed store into the (n0,m0) tile: column j of dv -> row
#pragma unroll
        for (int j = 0; j < 8; j++) {
            float* row = Dp + (size_t)(n0 + tx*8 + j) * NP + m0 + ty*8;
            *(float4*)row       = make_float4(dv[0][j], dv[1][j], dv[2][j], dv[3][j]);
            *(float4*)(row + 4) = make_float4(dv[4][j], dv[5][j], dv[6][j], dv[7][j]);
        }
    }
}

// ---------------- 6) pre2 as GEMM: [p2|q2] = f1 @ [W4a-W4b | W4b] ----------
#define PRE2_SMEM ((32*TS*2 + 128) * 4)
__global__ void __launch_bounds__(256) pre2_kernel(const float* __restrict__ W4,
                                                   const float* __restrict__ b4) {
    extern __shared__ float sm[];
    float* sAt = sm;
    float* sBt = sm + 32*TS;
    float* sBias = sm + 64*TS;
    int nblk = blockIdx.x;
    int m0 = blockIdx.y * 128;
    int tid = threadIdx.x;
    int tx = tid & 15, ty = tid >> 4;

    if (tid < 128) sBias[tid] = (nblk == 0) ? b4[tid] : 0.0f;

    float acc[8][8];
#pragma unroll
    for (int i = 0; i < 8; i++)
#pragma unroll
        for (int j = 0; j < 8; j++) acc[i][j] = 0.0f;

    for (int kc = 0; kc < 2; kc++) {
        __syncthreads();
#pragma unroll
        for (int l = 0; l < 16; l++) {
            int idx = l * 256 + tid;
            int r = idx >> 5, c = idx & 31;
            sAt[c * TS + r] = g_f1[(size_t)(m0 + r) * 64 + kc * 32 + c];
        }
#pragma unroll
        for (int l = 0; l < 16; l++) {
            int idx = l * 256 + tid;
            int nl = idx & 127, kk = idx >> 7;
            int k = kc * 32 + kk;
            float wb = W4[(64 + k) * 128 + nl];
            float w  = (nblk == 0) ? (W4[k * 128 + nl] - wb) : wb;
            sBt[kk * TS + nl] = w;
        }
        __syncthreads();
        for (int k = 0; k < 32; k++) {
            float4 a0 = *(const float4*)(sAt + k * TS + ty * 8);
            float4 a1 = *(const float4*)(sAt + k * TS + ty * 8 + 4);
            float4 c0 = *(const float4*)(sBt + k * TS + tx * 8);
            float4 c1 = *(const float4*)(sBt + k * TS + tx * 8 + 4);
            float a[8]  = {a0.x, a0.y, a0.z, a0.w, a1.x, a1.y, a1.z, a1.w};
            float bv[8] = {c0.x, c0.y, c0.z, c0.w, c1.x, c1.y, c1.z, c1.w};
#pragma unroll
            for (int i = 0; i < 8; i++)
#pragma unroll
                for (int j = 0; j < 8; j++) acc[i][j] = fmaf(a[i], bv[j], acc[i][j]);
        }
    }
    float* dst = (nblk == 0) ? g_p2 : g_q2;
    float bb[8];
#pragma unroll
    for (int j = 0; j < 8; j++) bb[j] = sBias[tx*8 + j];
#pragma unroll
    for (int i = 0; i < 8; i++) {
        float4 o0, o1;
        o0.x = acc[i][0] + bb[0]; o0.y = acc[i][1] + bb[1];
        o0.z = acc[i][2] + bb[2]; o0.w = acc[i][3] + bb[3];
        o1.x = acc[i][4] + bb[4]; o1.y = acc[i][5] + bb[5];
        o1.z = acc[i][6] + bb[6]; o1.w = acc[i][7] + bb[7];
        float* row = dst + (size_t)(m0 + ty*8 + i) * 128 + tx*8;
        *(float4*)row       = o0;
        *(float4*)(row + 4) = o1;
    }
}

// ---------------- 7) EdgeConv2: max_k relu(p + q) ---------------------------
__global__ void ec2_kernel() {
    int n = blockIdx.x, t = threadIdx.x;
    int b = n >> 10;
    float p = g_p2[(size_t)n * 128 + t];
    const int* idxp = g_idx + n * KNN;
    float best = 0.0f;
#pragma unroll
    for (int k = 0; k < KNN; k++) {
        int j = idxp[k];
        float q = g_q2[((size_t)(b << 10) + j) * 128 + t];
        best = fmaxf(best, p + q);
    }
    g_f2[(size_t)n * 128 + t] = best;
}

// ---------------- 8) pool: relu(f2@Wp+bp), max over points -----------------
__global__ void zero_pool_kernel() {
    int i = blockIdx.x * blockDim.x + threadIdx.x;
    if (i < BB * 512) g_pool[i] = 0.0f;
}

__global__ void pool_kernel(const float* __restrict__ Wp,
                            const float* __restrict__ bp) {
    __shared__ float sAt[32 * TS];
    __shared__ float sBt[32 * TS];
    __shared__ float sred[16 * 128];
    int m0 = blockIdx.x * 128, n0 = blockIdx.y * 128;
    int b  = m0 >> 10;
    int tid = threadIdx.x;
    int tx = tid & 15, ty = tid >> 4;

    float acc[8][8];
#pragma unroll
    for (int i = 0; i < 8; i++)
#pragma unroll
        for (int j = 0; j < 8; j++) acc[i][j] = 0.0f;

    for (int kc = 0; kc < 4; kc++) {
        __syncthreads();
#pragma unroll
        for (int l = 0; l < 16; l++) {
            int idx = l * 256 + tid;
            int r = idx >> 5, c = idx & 31;
            sAt[c * TS + r] = g_f2[(size_t)(m0 + r) * 128 + kc * 32 + c];
        }
#pragma unroll
        for (int l = 0; l < 16; l++) {
            int idx = l * 256 + tid;
            int nl = idx & 127, kk = idx >> 7;
            sBt[kk * TS + nl] = Wp[(size_t)(kc * 32 + kk) * 512 + n0 + nl];
        }
        __syncthreads();
        for (int k = 0; k < 32; k++) {
            float4 a0 = *(const float4*)(sAt + k * TS + ty * 8);
            float4 a1 = *(const float4*)(sAt + k * TS + ty * 8 + 4);
            float4 c0 = *(const float4*)(sBt + k * TS + tx * 8);
            float4 c1 = *(const float4*)(sBt + k * TS + tx * 8 + 4);
            float a[8]  = {a0.x, a0.y, a0.z, a0.w, a1.x, a1.y, a1.z, a1.w};
            float bv[8] = {c0.x, c0.y, c0.z, c0.w, c1.x, c1.y, c1.z, c1.w};
#pragma unroll
            for (int i = 0; i < 8; i++)
#pragma unroll
                for (int j = 0; j < 8; j++) acc[i][j] = fmaf(a[i], bv[j], acc[i][j]);
        }
    }
#pragma unroll
    for (int j = 0; j < 8; j++) {
        int col = n0 + tx * 8 + j;
        float bpv = bp[col];
        float cm = 0.0f;
#pragma unroll
        for (int i = 0; i < 8; i++) cm = fmaxf(cm, acc[i][j] + bpv);
        sred[ty * 128 + tx * 8 + j] = cm;
    }
    __syncthreads();
    if (ty == 0) {
#pragma unroll
        for (int j = 0; j < 8; j++) {
            float cm = 0.0f;
#pragma unroll
            for (int yy = 0; yy < 16; yy++) cm = fmaxf(cm, sred[yy * 128 + tx * 8 + j]);
            atomicMax((int*)&g_pool[b * 512 + n0 + tx * 8 + j], __float_as_int(cm));
        }
    }
}

// ---------------- 9) classifier head ----------------------------------------
__global__ void head_kernel(const float* __restrict__ Wt1, const float* __restrict__ bt1,
                            const float* __restrict__ Wt2, const float* __restrict__ bt2,
                            float* __restrict__ out) {
    __shared__ float sp[512];
    __shared__ float st[256];
    int b = blockIdx.x, t = threadIdx.x;
    sp[t]       = g_pool[b * 512 + t];
    sp[256 + t] = g_pool[b * 512 + 256 + t];
    __syncthreads();
    float acc = bt1[t];
#pragma unroll 8
    for (int c = 0; c < 512; c++) acc = fmaf(sp[c], Wt1[c * 256 + t], acc);
    st[t] = fmaxf(acc, 0.0f);
    __syncthreads();
    if (t < 40) {
        float a2 = bt2[t];
#pragma unroll 8
        for (int c = 0; c < 256; c++) a2 = fmaf(st[c], Wt2[c * 40 + t], a2);
        out[b * 40 + t] = a2;
    }
}

// ---------------- launch -----------------------------------------------------
extern "C" void kernel_launch(void* const* d_in, const int* in_sizes, int n_in,
                              void* d_out, int out_size) {
    const float* x   = (const float*)d_in[0];
    const float* W1  = (const float*)d_in[2];
    const float* b1  = (const float*)d_in[3];
    const float* W2  = (const float*)d_in[4];
    const float* b2  = (const float*)d_in[5];
    const float* W3  = (const float*)d_in[6];
    const float* b3  = (const float*)d_in[7];
    const float* W4  = (const float*)d_in[8];
    const float* b4  = (const float*)d_in[9];
    const float* Wp  = (const float*)d_in[10];
    const float* bp  = (const float*)d_in[11];
    const float* Wt1 = (const float*)d_in[12];
    const float* bt1 = (const float*)d_in[13];
    const float* Wt2 = (const float*)d_in[14];
    const float* bt2 = (const float*)d_in[15];
    float* out = (float*)d_out;

    cudaFuncSetAttribute(ec1_kernel,    cudaFuncAttributeMaxDynamicSharedMemorySize, EC1_SMEM);
    cudaFuncSetAttribute(dist64_kernel, cudaFuncAttributeMaxDynamicSharedMemorySize, D64_SMEM);
    cudaFuncSetAttribute(pre2_kernel,   cudaFuncAttributeMaxDynamicSharedMemorySize, PRE2_SMEM);

    // Stage 1
    knn3_kernel<<<NPTS / 8, 256>>>(x);
    pre1_kernel<<<(NPTS * 64) / 256, 256>>>(x, W1, b1);
    ec1_kernel<<<NEDGE / 256, 256, EC1_SMEM>>>(W2, b2, W3, b3);

    // Stage 2
    norm64_kernel<<<NPTS / 256, 256>>>();
    dist64_kernel<<<dim3(36, BB), 256, D64_SMEM>>>();
    topk_kernel<<<NPTS / 8, 256>>>();
    pre2_kernel<<<dim3(2, 256), 256, PRE2_SMEM>>>(W4, b4);
    ec2_kernel<<<NPTS, 128>>>();

    // Stage 3
    zero_pool_kernel<<<16, 1024>>>();
    pool_kernel<<<dim3(256, 4), 256>>>(Wp, bp);
    head_kernel<<<BB, 256>>>(Wt1, bt1, Wt2, bt2, out);
}

// round 8
// speedup vs baseline: 1.4441x; 1.0083x over previous
#include <cuda_runtime.h>
#include <math_constants.h>

#define BB   32
#define NP   1024
#define KNN  20
#define NPTS (BB*NP)
#define NEDGE (NPTS*KNN)

// ---------------- scratch (device globals; no allocation allowed) ----------
__device__ float g_D[(size_t)BB*NP*NP];
__device__ int   g_idx[NPTS*KNN];
__device__ float g_p1[NPTS*64];
__device__ float g_q1[NPTS*64];
__device__ float g_f1[NPTS*64];
__device__ float g_norm[NPTS];
__device__ float g_p2[NPTS*128];
__device__ float g_q2[NPTS*128];
__device__ float g_f2[NPTS*128];
__device__ float g_pool[BB*512];

// ---------------- 1) fused kNN on xyz ----------------
__global__ void __launch_bounds__(256) knn3_kernel(const float* __restrict__ x) {
    __shared__ float sx[NP], sy[NP], sz[NP], sq[NP];
    int rowBase = blockIdx.x * 8;
    int b = rowBase >> 10;
    const float* xb = x + (size_t)b * NP * 3;
    for (int i = threadIdx.x; i < NP; i += 256) {
        float a0 = xb[i*3], a1 = xb[i*3+1], a2 = xb[i*3+2];
        sx[i] = a0; sy[i] = a1; sz[i] = a2;
        sq[i] = a0*a0 + a1*a1 + a2*a2;
    }
    __syncthreads();
    int warp = threadIdx.x >> 5, lane = threadIdx.x & 31;
    int n  = rowBase + warp;
    int nl = n & (NP - 1);
    float qx = sx[nl], qy = sy[nl], qz = sz[nl], qs = sq[nl];
    float v[32];
#pragma unroll
    for (int i = 0; i < 32; i++) {
        int m = lane + (i << 5);
        float d = qs + sq[m] - 2.0f * (qx*sx[m] + qy*sy[m] + qz*sz[m]);
        v[i] = (m == nl) ? CUDART_INF_F : d;
    }
    float bv = v[0]; int bi = 0;
#pragma unroll
    for (int i = 1; i < 32; i++) if (v[i] < bv) { bv = v[i]; bi = i; }
    for (int r = 0; r < KNN; r++) {
        float mv = bv; int mi = (bi << 5) | lane;
#pragma unroll
        for (int off = 16; off > 0; off >>= 1) {
            float ov = __shfl_down_sync(0xffffffffu, mv, off);
            int   oi = __shfl_down_sync(0xffffffffu, mi, off);
            if (ov < mv || (ov == mv && oi < mi)) { mv = ov; mi = oi; }
        }
        mi = __shfl_sync(0xffffffffu, mi, 0);
        if (lane == 0) g_idx[n * KNN + r] = mi;
        if ((mi & 31) == lane) {
            int slot = mi >> 5;
#pragma unroll
            for (int i = 0; i < 32; i++) if (i == slot) v[i] = CUDART_INF_F;
            bv = v[0]; bi = 0;
#pragma unroll
            for (int i = 1; i < 32; i++) if (v[i] < bv) { bv = v[i]; bi = i; }
        }
    }
}

// ---------------- 2) top-20 per row of g_D (self excluded here) ------------
__global__ void topk_kernel() {
    int row  = blockIdx.x * 8 + (threadIdx.x >> 5);
    int lane = threadIdx.x & 31;
    int nl = row & (NP - 1);
    const float* d = g_D + (size_t)row * NP;
    float v[32];
#pragma unroll
    for (int i = 0; i < 32; i++) {
        int m = lane + (i << 5);
        v[i] = (m == nl) ? CUDART_INF_F : d[m];
    }
    float bv = v[0]; int bi = 0;
#pragma unroll
    for (int i = 1; i < 32; i++) if (v[i] < bv) { bv = v[i]; bi = i; }
    for (int r = 0; r < KNN; r++) {
        float mv = bv; int mi = (bi << 5) | lane;
#pragma unroll
        for (int off = 16; off > 0; off >>= 1) {
            float ov = __shfl_down_sync(0xffffffffu, mv, off);
            int   oi = __shfl_down_sync(0xffffffffu, mi, off);
            if (ov < mv || (ov == mv && oi < mi)) { mv = ov; mi = oi; }
        }
        mi = __shfl_sync(0xffffffffu, mi, 0);
        if (lane == 0) g_idx[row * KNN + r] = mi;
        if ((mi & 31) == lane) {
            int slot = mi >> 5;
#pragma unroll
            for (int i = 0; i < 32; i++) if (i == slot) v[i] = CUDART_INF_F;
            bv = v[0]; bi = 0;
#pragma unroll
            for (int i = 1; i < 32; i++) if (v[i] < bv) { bv = v[i]; bi = i; }
        }
    }
}

// ---------------- 3) EdgeConv1 layer-1 split precompute (+ zero f1) --------
__global__ void pre1_kernel(const float* __restrict__ x,
                            const float* __restrict__ W1,
                            const float* __restrict__ b1) {
    int id = blockIdx.x * blockDim.x + threadIdx.x;
    if (id >= NPTS * 64) return;
    int n = id >> 6, t = id & 63;
    float x0 = x[n*3], x1 = x[n*3+1], x2 = x[n*3+2];
    float wa0 = W1[t],       wa1 = W1[64 + t],  wa2 = W1[128 + t];
    float wb0 = W1[192 + t], wb1 = W1[256 + t], wb2 = W1[320 + t];
    float q = x0*wb0 + x1*wb1 + x2*wb2;
    float p = b1[t] + x0*(wa0-wb0) + x1*(wa1-wb1) + x2*(wa2-wb2);
    g_p1[id] = p;
    g_q1[id] = q;
    g_f1[id] = 0.0f;
}

// ---------------- 4) EdgeConv1 fused 2-layer GEMM over 256-edge tiles ------
#define ETP 260
#define EC1_SMEM ((64*ETP + 4096 + 4096 + 64 + 64) * 4)
__global__ void __launch_bounds__(256, 2) ec1_kernel(const float* __restrict__ W2,
                                                     const float* __restrict__ b2,
                                                     const float* __restrict__ W3,
                                                     const float* __restrict__ b3) {
    extern __shared__ float sm[];
    float* ET  = sm;
    float* sW2 = sm + 64*ETP;
    float* sW3 = sW2 + 4096;
    float* sB2 = sW3 + 4096;
    float* sB3 = sB2 + 64;
    int tid = threadIdx.x;
    int tx = tid & 7, ty = tid >> 3;

    for (int i = tid; i < 4096; i += 256) { sW2[i] = W2[i]; sW3[i] = W3[i]; }
    if (tid < 64) { sB2[tid] = b2[tid]; sB3[tid] = b3[tid]; }

    int B0 = blockIdx.x * 256;
    int g  = B0 + tid;
    int p  = g / KNN;
    int b  = p >> 10;
    int j  = g_idx[g];
    const float* pr = g_p1 + (size_t)p * 64;
    const float* qr = g_q1 + ((size_t)(b << 10) + j) * 64;
    __syncthreads();
#pragma unroll
    for (int c = 0; c < 64; c += 4) {
        float4 pv = *(const float4*)(pr + c);
        float4 qv = *(const float4*)(qr + c);
        ET[(c+0)*ETP + tid] = fmaxf(pv.x + qv.x, 0.0f);
        ET[(c+1)*ETP + tid] = fmaxf(pv.y + qv.y, 0.0f);
        ET[(c+2)*ETP + tid] = fmaxf(pv.z + qv.z, 0.0f);
        ET[(c+3)*ETP + tid] = fmaxf(pv.w + qv.w, 0.0f);
    }
    __syncthreads();

    float acc[8][8];
#pragma unroll
    for (int i = 0; i < 8; i++)
#pragma unroll
        for (int jj = 0; jj < 8; jj++) acc[i][jj] = 0.0f;
#pragma unroll 4
    for (int k = 0; k < 64; k++) {
        float4 a0 = *(const float4*)(ET + k*ETP + ty*8);
        float4 a1 = *(const float4*)(ET + k*ETP + ty*8 + 4);
        float4 w0 = *(const float4*)(sW2 + k*64 + tx*8);
        float4 w1 = *(const float4*)(sW2 + k*64 + tx*8 + 4);
        float a[8] = {a0.x,a0.y,a0.z,a0.w,a1.x,a1.y,a1.z,a1.w};
        float w[8] = {w0.x,w0.y,w0.z,w0.w,w1.x,w1.y,w1.z,w1.w};
#pragma unroll
        for (int i = 0; i < 8; i++)
#pragma unroll
            for (int jj = 0; jj < 8; jj++) acc[i][jj] = fmaf(a[i], w[jj], acc[i][jj]);
    }
    float bv2[8], bv3[8];
#pragma unroll
    for (int jj = 0; jj < 8; jj++) { bv2[jj] = sB2[tx*8+jj]; bv3[jj] = sB3[tx*8+jj]; }
    __syncthreads();
#pragma unroll
    for (int jj = 0; jj < 8; jj++)
#pragma unroll
        for (int i = 0; i < 8; i++)
            ET[(tx*8+jj)*ETP + ty*8 + i] = fmaxf(acc[i][jj] + bv2[jj], 0.0f);
    __syncthreads();

#pragma unroll
    for (int i = 0; i < 8; i++)
#pragma unroll
        for (int jj = 0; jj < 8; jj++) acc[i][jj] = 0.0f;
#pragma unroll 4
    for (int k = 0; k < 64; k++) {
        float4 a0 = *(const float4*)(ET + k*ETP + ty*8);
        float4 a1 = *(const float4*)(ET + k*ETP + ty*8 + 4);
        float4 w0 = *(const float4*)(sW3 + k*64 + tx*8);
        float4 w1 = *(const float4*)(sW3 + k*64 + tx*8 + 4);
        float a[8] = {a0.x,a0.y,a0.z,a0.w,a1.x,a1.y,a1.z,a1.w};
        float w[8] = {w0.x,w0.y,w0.z,w0.w,w1.x,w1.y,w1.z,w1.w};
#pragma unroll
        for (int i = 0; i < 8; i++)
#pragma unroll
            for (int jj = 0; jj < 8; jj++) acc[i][jj] = fmaf(a[i], w[jj], acc[i][jj]);
    }
    __syncthreads();
#pragma unroll
    for (int i = 0; i < 8; i++) {
        float4 v0, v1;
        v0.x = acc[i][0] + bv3[0]; v0.y = acc[i][1] + bv3[1];
        v0.z = acc[i][2] + bv3[2]; v0.w = acc[i][3] + bv3[3];
        v1.x = acc[i][4] + bv3[4]; v1.y = acc[i][5] + bv3[5];
        v1.z = acc[i][6] + bv3[6]; v1.w = acc[i][7] + bv3[7];
        *(float4*)(ET + (ty*8+i)*64 + tx*8)     = v0;
        *(float4*)(ET + (ty*8+i)*64 + tx*8 + 4) = v1;
    }
    __syncthreads();

    int pFirst = B0 / KNN;
    int pLast  = (B0 + 255) / KNN;
    int nseg   = pLast - pFirst + 1;
    int ch = tid & 63;
    for (int s = tid >> 6; s < nseg; s += 4) {
        int pt = pFirst + s;
        int r0 = max(pt * KNN,       B0) - B0;
        int r1 = min(pt * KNN + KNN, B0 + 256) - B0;
        if (r0 >= r1) continue;
        float m = ET[r0*64 + ch];
        for (int r = r0 + 1; r < r1; r++) m = fmaxf(m, ET[r*64 + ch]);
        atomicMax((int*)&g_f1[(size_t)pt*64 + ch], __float_as_int(m));
    }
}

// ---------------- 4b) squared norms of f1 rows ------------------------------
__global__ void norm64_kernel() {
    int n = blockIdx.x * 256 + threadIdx.x;
    const float4* r = (const float4*)(g_f1 + (size_t)n * 64);
    float s = 0.0f;
#pragma unroll
    for (int i = 0; i < 16; i++) {
        float4 v = r[i];
        s += v.x*v.x + v.y*v.y + v.z*v.z + v.w*v.w;
    }
    g_norm[n] = s;
}

// ---------------- 5) dist64: SYMMETRIC Gram GEMM (ti<=tj), dual store -------
#define TS 132
#define D64_SMEM ((32*TS*2 + 256) * 4)
__global__ void __launch_bounds__(256) dist64_kernel() {
    extern __shared__ float sm[];
    float* sAt = sm;
    float* sBt = sm + 32*TS;
    float* snA = sm + 64*TS;
    float* snB = snA + 128;
    int b = blockIdx.y;
    int t = blockIdx.x, ti = 0;
    while (t >= 8 - ti) { t -= 8 - ti; ti++; }
    int tj = ti + t;
    int m0 = ti * 128, n0 = tj * 128;
    int tid = threadIdx.x;
    int tx = tid & 15, ty = tid >> 4;
    const float* F = g_f1 + (size_t)b * NP * 64;

    if (tid < 128)      snA[tid]       = g_norm[b*NP + m0 + tid];
    else                snB[tid - 128] = g_norm[b*NP + n0 + tid - 128];

    float acc[8][8];
#pragma unroll
    for (int i = 0; i < 8; i++)
#pragma unroll
        for (int j = 0; j < 8; j++) acc[i][j] = 0.0f;

    for (int kc = 0; kc < 2; kc++) {
        __syncthreads();
#pragma unroll
        for (int l = 0; l < 16; l++) {
            int idx = l * 256 + tid;
            int r = idx >> 5, c = idx & 31;
            sAt[c * TS + r] = F[(size_t)(m0 + r) * 64 + kc * 32 + c];
            sBt[c * TS + r] = F[(size_t)(n0 + r) * 64 + kc * 32 + c];
        }
        __syncthreads();
        for (int k = 0; k < 32; k++) {
            float4 a0 = *(const float4*)(sAt + k * TS + ty * 8);
            float4 a1 = *(const float4*)(sAt + k * TS + ty * 8 + 4);
            float4 c0 = *(const float4*)(sBt + k * TS + tx * 8);
            float4 c1 = *(const float4*)(sBt + k * TS + tx * 8 + 4);
            float a[8]  = {a0.x, a0.y, a0.z, a0.w, a1.x, a1.y, a1.z, a1.w};
            float bv[8] = {c0.x, c0.y, c0.z, c0.w, c1.x, c1.y, c1.z, c1.w};
#pragma unroll
            for (int i = 0; i < 8; i++)
#pragma unroll
                for (int j = 0; j < 8; j++) acc[i][j] = fmaf(a[i], bv[j], acc[i][j]);
        }
    }
    float* Dp = g_D + (size_t)b * NP * NP;
    float nb_[8];
#pragma unroll
    for (int j = 0; j < 8; j++) nb_[j] = snB[tx*8 + j];

    float dv[8][8];
#pragma unroll
    for (int i = 0; i < 8; i++) {
        float nai = snA[ty*8 + i];
#pragma unroll
        for (int j = 0; j < 8; j++) dv[i][j] = nai + nb_[j] - 2.0f * acc[i][j];
    }
#pragma unroll
    for (int i = 0; i < 8; i++) {
        float* row = Dp + (size_t)(m0 + ty*8 + i) * NP + n0 + tx*8;
        *(float4*)row       = make_float4(dv[i][0], dv[i][1], dv[i][2], dv[i][3]);
        *(float4*)(row + 4) = make_float4(dv[i][4], dv[i][5], dv[i][6], dv[i][7]);
    }
    if (ti != tj) {
#pragma unroll
        for (int j = 0; j < 8; j++) {
            float* row = Dp + (size_t)(n0 + tx*8 + j) * NP + m0 + ty*8;
            *(float4*)row       = make_float4(dv[0][j], dv[1][j], dv[2][j], dv[3][j]);
            *(float4*)(row + 4) = make_float4(dv[4][j], dv[5][j], dv[6][j], dv[7][j]);
        }
    }
}

// ---------------- 6) pre2 as GEMM: [p2|q2] = f1 @ [W4a-W4b | W4b] ----------
#define PRE2_SMEM ((32*TS*2 + 128) * 4)
__global__ void __launch_bounds__(256) pre2_kernel(const float* __restrict__ W4,
                                                   const float* __restrict__ b4) {
    extern __shared__ float sm[];
    float* sAt = sm;
    float* sBt = sm + 32*TS;
    float* sBias = sm + 64*TS;
    int nblk = blockIdx.x;
    int m0 = blockIdx.y * 128;
    int tid = threadIdx.x;
    int tx = tid & 15, ty = tid >> 4;

    if (tid < 128) sBias[tid] = (nblk == 0) ? b4[tid] : 0.0f;

    float acc[8][8];
#pragma unroll
    for (int i = 0; i < 8; i++)
#pragma unroll
        for (int j = 0; j < 8; j++) acc[i][j] = 0.0f;

    for (int kc = 0; kc < 2; kc++) {
        __syncthreads();
#pragma unroll
        for (int l = 0; l < 16; l++) {
            int idx = l * 256 + tid;
            int r = idx >> 5, c = idx & 31;
            sAt[c * TS + r] = g_f1[(size_t)(m0 + r) * 64 + kc * 32 + c];
        }
#pragma unroll
        for (int l = 0; l < 16; l++) {
            int idx = l * 256 + tid;
            int nl = idx & 127, kk = idx >> 7;
            int k = kc * 32 + kk;
            float wb = W4[(64 + k) * 128 + nl];
            float w  = (nblk == 0) ? (W4[k * 128 + nl] - wb) : wb;
            sBt[kk * TS + nl] = w;
        }
        __syncthreads();
        for (int k = 0; k < 32; k++) {
            float4 a0 = *(const float4*)(sAt + k * TS + ty * 8);
            float4 a1 = *(const float4*)(sAt + k * TS + ty * 8 + 4);
            float4 c0 = *(const float4*)(sBt + k * TS + tx * 8);
            float4 c1 = *(const float4*)(sBt + k * TS + tx * 8 + 4);
            float a[8]  = {a0.x, a0.y, a0.z, a0.w, a1.x, a1.y, a1.z, a1.w};
            float bv[8] = {c0.x, c0.y, c0.z, c0.w, c1.x, c1.y, c1.z, c1.w};
#pragma unroll
            for (int i = 0; i < 8; i++)
#pragma unroll
                for (int j = 0; j < 8; j++) acc[i][j] = fmaf(a[i], bv[j], acc[i][j]);
        }
    }
    float* dst = (nblk == 0) ? g_p2 : g_q2;
    float bb[8];
#pragma unroll
    for (int j = 0; j < 8; j++) bb[j] = sBias[tx*8 + j];
#pragma unroll
    for (int i = 0; i < 8; i++) {
        float4 o0, o1;
        o0.x = acc[i][0] + bb[0]; o0.y = acc[i][1] + bb[1];
        o0.z = acc[i][2] + bb[2]; o0.w = acc[i][3] + bb[3];
        o1.x = acc[i][4] + bb[4]; o1.y = acc[i][5] + bb[5];
        o1.z = acc[i][6] + bb[6]; o1.w = acc[i][7] + bb[7];
        float* row = dst + (size_t)(m0 + ty*8 + i) * 128 + tx*8;
        *(float4*)row       = o0;
        *(float4*)(row + 4) = o1;
    }
}

// ---------------- 7) EdgeConv2: max_k relu(p + q) ---------------------------
__global__ void ec2_kernel() {
    int n = blockIdx.x, t = threadIdx.x;
    int b = n >> 10;
    float p = g_p2[(size_t)n * 128 + t];
    const int* idxp = g_idx + n * KNN;
    float best = 0.0f;
#pragma unroll
    for (int k = 0; k < KNN; k++) {
        int j = idxp[k];
        float q = g_q2[((size_t)(b << 10) + j) * 128 + t];
        best = fmaxf(best, p + q);
    }
    g_f2[(size_t)n * 128 + t] = best;
}

// ---------------- 8) pool: relu(f2@Wp+bp), max over points -----------------
__global__ void zero_pool_kernel() {
    int i = blockIdx.x * blockDim.x + threadIdx.x;
    if (i < BB * 512) g_pool[i] = 0.0f;
}

__global__ void pool_kernel(const float* __restrict__ Wp,
                            const float* __restrict__ bp) {
    __shared__ float sAt[32 * TS];
    __shared__ float sBt[32 * TS];
    __shared__ float sred[16 * 128];
    int m0 = blockIdx.x * 128, n0 = blockIdx.y * 128;
    int b  = m0 >> 10;
    int tid = threadIdx.x;
    int tx = tid & 15, ty = tid >> 4;

    float acc[8][8];
#pragma unroll
    for (int i = 0; i < 8; i++)
#pragma unroll
        for (int j = 0; j < 8; j++) acc[i][j] = 0.0f;

    for (int kc = 0; kc < 4; kc++) {
        __syncthreads();
#pragma unroll
        for (int l = 0; l < 16; l++) {
            int idx = l * 256 + tid;
            int r = idx >> 5, c = idx & 31;
            sAt[c * TS + r] = g_f2[(size_t)(m0 + r) * 128 + kc * 32 + c];
        }
#pragma unroll
        for (int l = 0; l < 16; l++) {
            int idx = l * 256 + tid;
            int nl = idx & 127, kk = idx >> 7;
            sBt[kk * TS + nl] = Wp[(size_t)(kc * 32 + kk) * 512 + n0 + nl];
        }
        __syncthreads();
        for (int k = 0; k < 32; k++) {
            float4 a0 = *(const float4*)(sAt + k * TS + ty * 8);
            float4 a1 = *(const float4*)(sAt + k * TS + ty * 8 + 4);
            float4 c0 = *(const float4*)(sBt + k * TS + tx * 8);
            float4 c1 = *(const float4*)(sBt + k * TS + tx * 8 + 4);
            float a[8]  = {a0.x, a0.y, a0.z, a0.w, a1.x, a1.y, a1.z, a1.w};
            float bv[8] = {c0.x, c0.y, c0.z, c0.w, c1.x, c1.y, c1.z, c1.w};
#pragma unroll
            for (int i = 0; i < 8; i++)
#pragma unroll
                for (int j = 0; j < 8; j++) acc[i][j] = fmaf(a[i], bv[j], acc[i][j]);
        }
    }
#pragma unroll
    for (int j = 0; j < 8; j++) {
        int col = n0 + tx * 8 + j;
        float bpv = bp[col];
        float cm = 0.0f;
#pragma unroll
        for (int i = 0; i < 8; i++) cm = fmaxf(cm, acc[i][j] + bpv);
        sred[ty * 128 + tx * 8 + j] = cm;
    }
    __syncthreads();
    if (ty == 0) {
#pragma unroll
        for (int j = 0; j < 8; j++) {
            float cm = 0.0f;
#pragma unroll
            for (int yy = 0; yy < 16; yy++) cm = fmaxf(cm, sred[yy * 128 + tx * 8 + j]);
            atomicMax((int*)&g_pool[b * 512 + n0 + tx * 8 + j], __float_as_int(cm));
        }
    }
}

// ---------------- 9) classifier head ----------------------------------------
__global__ void head_kernel(const float* __restrict__ Wt1, const float* __restrict__ bt1,
                            const float* __restrict__ Wt2, const float* __restrict__ bt2,
                            float* __restrict__ out) {
    __shared__ float sp[512];
    __shared__ float st[256];
    int b = blockIdx.x, t = threadIdx.x;
    sp[t]       = g_pool[b * 512 + t];
    sp[256 + t] = g_pool[b * 512 + 256 + t];
    __syncthreads();
    float acc = bt1[t];
#pragma unroll 8
    for (int c = 0; c < 512; c++) acc = fmaf(sp[c], Wt1[c * 256 + t], acc);
    st[t] = fmaxf(acc, 0.0f);
    __syncthreads();
    if (t < 40) {
        float a2 = bt2[t];
#pragma unroll 8
        for (int c = 0; c < 256; c++) a2 = fmaf(st[c], Wt2[c * 40 + t], a2);
        out[b * 40 + t] = a2;
    }
}

// ---------------- launch: fork/join overlap of independent kernels ----------
extern "C" void kernel_launch(void* const* d_in, const int* in_sizes, int n_in,
                              void* d_out, int out_size) {
    const float* x   = (const float*)d_in[0];
    const float* W1  = (const float*)d_in[2];
    const float* b1  = (const float*)d_in[3];
    const float* W2  = (const float*)d_in[4];
    const float* b2  = (const float*)d_in[5];
    const float* W3  = (const float*)d_in[6];
    const float* b3  = (const float*)d_in[7];
    const float* W4  = (const float*)d_in[8];
    const float* b4  = (const float*)d_in[9];
    const float* Wp  = (const float*)d_in[10];
    const float* bp  = (const float*)d_in[11];
    const float* Wt1 = (const float*)d_in[12];
    const float* bt1 = (const float*)d_in[13];
    const float* Wt2 = (const float*)d_in[14];
    const float* bt2 = (const float*)d_in[15];
    float* out = (float*)d_out;

    // one-time resource setup (no device memory involved)
    static cudaStream_t s1 = nullptr, s2 = nullptr;
    static cudaEvent_t evRoot = nullptr, evPre1 = nullptr, evEc1 = nullptr,
                       evPre2 = nullptr, evZero = nullptr;
    if (s1 == nullptr) {
        cudaStreamCreateWithFlags(&s1, cudaStreamNonBlocking);
        cudaStreamCreateWithFlags(&s2, cudaStreamNonBlocking);
        cudaEventCreateWithFlags(&evRoot, cudaEventDisableTiming);
        cudaEventCreateWithFlags(&evPre1, cudaEventDisableTiming);
        cudaEventCreateWithFlags(&evEc1,  cudaEventDisableTiming);
        cudaEventCreateWithFlags(&evPre2, cudaEventDisableTiming);
        cudaEventCreateWithFlags(&evZero, cudaEventDisableTiming);
        cudaFuncSetAttribute(ec1_kernel,    cudaFuncAttributeMaxDynamicSharedMemorySize, EC1_SMEM);
        cudaFuncSetAttribute(dist64_kernel, cudaFuncAttributeMaxDynamicSharedMemorySize, D64_SMEM);
        cudaFuncSetAttribute(pre2_kernel,   cudaFuncAttributeMaxDynamicSharedMemorySize, PRE2_SMEM);
    }

    // fork side streams off the capture-origin (legacy) stream
    cudaEventRecord(evRoot, 0);
    cudaStreamWaitEvent(s1, evRoot, 0);
    cudaStreamWaitEvent(s2, evRoot, 0);

    // s2: zero g_pool (joined before pool_kernel)
    zero_pool_kernel<<<16, 1024, 0, s2>>>();
    cudaEventRecord(evZero, s2);

    // s1: pre1 (only needs x)  ||  main: knn3
    pre1_kernel<<<(NPTS * 64) / 256, 256, 0, s1>>>(x, W1, b1);
    cudaEventRecord(evPre1, s1);
    knn3_kernel<<<NPTS / 8, 256>>>(x);

    // join pre1, run ec1 (needs idx + p1/q1/f1-zero)
    cudaStreamWaitEvent(0, evPre1, 0);
    ec1_kernel<<<NEDGE / 256, 256, EC1_SMEM>>>(W2, b2, W3, b3);

    // fork pre2 (needs only f1)  ||  main: norm64 -> dist64 -> topk
    cudaEventRecord(evEc1, 0);
    cudaStreamWaitEvent(s1, evEc1, 0);
    pre2_kernel<<<dim3(2, 256), 256, PRE2_SMEM, s1>>>(W4, b4);
    cudaEventRecord(evPre2, s1);

    norm64_kernel<<<NPTS / 256, 256>>>();
    dist64_kernel<<<dim3(36, BB), 256, D64_SMEM>>>();
    topk_kernel<<<NPTS / 8, 256>>>();

    // join pre2, run ec2 (needs idx + p2/q2)
    cudaStreamWaitEvent(0, evPre2, 0);
    ec2_kernel<<<NPTS, 128>>>();

    // join zero_pool, run pool + head
    cudaStreamWaitEvent(0, evZero, 0);
    pool_kernel<<<dim3(256, 4), 256>>>(Wp, bp);
    head_kernel<<<BB, 256>>>(Wt1, bt1, Wt2, bt2, out);
}